// round 13
// baseline (speedup 1.0000x reference)
#include <cuda_runtime.h>
#include <cstdint>

#define B_      64
#define CIN     64
#define COUT    64
#define IMG     32
#define POS     1024
#define CCH     4                  // channels per chunk
#define NCH     16                 // 64 / 4
#define WSTRIDE 148                // floats per o-row in W stage (4*36 + 4 pad)
#define WBUF_F  (64 * WSTRIDE)     // 9472 floats per W buffer (x2)
#define XSTRIDE 12                 // floats per (g,b) row in X stage (8 used)
#define XBUF_F  (12 * 64 * XSTRIDE) // 9216 floats (single buffer)
#define XBASE_F (2 * WBUF_F)       // 18944
#define SMEM_F  (XBASE_F + XBUF_F) // 28160 floats
#define SMEM_BYTES (SMEM_F * 4)    // 112640

__device__ float g_yt[(size_t)COUT * POS * B_];
__device__ float g_partS[COUT * 256];
__device__ float g_partQ[COUT * 256];
__device__ float g_sum[COUT];
__device__ float g_sumsq[COUT];

__device__ __forceinline__ uint32_t to_tf32(float f) {
    uint32_t r;
    asm("cvt.rna.tf32.f32 %0, %1;" : "=r"(r) : "f"(f));
    return r;
}
__device__ __forceinline__ void mma8(float* c, const uint32_t* a,
                                     uint32_t b0, uint32_t b1) {
    asm volatile(
        "mma.sync.aligned.m16n8k8.row.col.f32.tf32.tf32.f32 "
        "{%0,%1,%2,%3}, {%4,%5,%6,%7}, {%8,%9}, {%0,%1,%2,%3};"
        : "+f"(c[0]), "+f"(c[1]), "+f"(c[2]), "+f"(c[3])
        : "r"(a[0]), "r"(a[1]), "r"(a[2]), "r"(a[3]), "r"(b0), "r"(b1));
}
__device__ __forceinline__ uint32_t sptr(const void* p) {
    uint32_t a;
    asm("{ .reg .u64 t; cvta.to.shared.u64 t, %1; cvt.u32.u64 %0, t; }" : "=r"(a) : "l"(p));
    return a;
}
__device__ __forceinline__ void cp16(uint32_t dst, const void* src) {
    asm volatile("cp.async.cg.shared.global [%0], [%1], 16;"
                 :: "r"(dst), "l"(src) : "memory");
}
#define CP_COMMIT() asm volatile("cp.async.commit_group;" ::: "memory")
#define CP_WAIT(N)  asm volatile("cp.async.wait_group %0;" :: "n"(N) : "memory")

// cp.async one chunk of weights: 256 granules (o,cl) x 9 float4 = 2304 (exact)
__device__ __forceinline__ void stage_w(const float* __restrict__ w,
                                        int c0, int posb, int t, uint32_t wdst)
{
#pragma unroll
    for (int it = 0; it < 9; ++it) {
        const int f  = t + it * 256;
        const int go = f / 9;
        const int r  = f - go * 9;
        const int o  = go >> 2, cl = go & 3;
        const float* src = w + ((size_t)(o * CIN + c0 + cl) * POS + posb) * 9 + r * 4;
        cp16(wdst + (uint32_t)((o * WSTRIDE + cl * 36 + r * 4) * 4), src);
    }
    CP_COMMIT();
}

// guarded x loads for one chunk into registers (12 float2 / thread)
__device__ __forceinline__ void load_x(const float* __restrict__ x,
                                       int c0, int i, int j0, int t, float2* rx)
{
#pragma unroll
    for (int l = 0; l < 12; ++l) {
        const int f     = t + l * 256;
        const int q     = f & 3;
        const int rowid = f >> 2;
        const int b     = rowid & 63;
        const int g     = rowid >> 6;      // cl*3+u, 0..11
        const int cl    = g / 3;
        const int u     = g - cl * 3;
        const int row   = i - 1 + u;
        const int col   = j0 - 2 + 2 * q;
        float2 v = make_float2(0.f, 0.f);
        const bool ok = ((unsigned)row < IMG) &&
                        !(q == 0 && j0 == 0) && !(q == 3 && j0 == 28);
        if (ok)
            v = *(const float2*)(x + ((size_t)(b * CIN + c0 + cl) * IMG + row) * IMG + col);
        rx[l] = v;
    }
}

// unconditional STS of prefetched x registers, pre-converted to tf32 bits
__device__ __forceinline__ void store_x(uint32_t* xbuf, int t, const float2* rx)
{
#pragma unroll
    for (int l = 0; l < 12; ++l) {
        const int f     = t + l * 256;
        const int q     = f & 3;
        const int rowid = f >> 2;
        uint2 e;
        e.x = to_tf32(rx[l].x);
        e.y = to_tf32(rx[l].y);
        *(uint2*)(xbuf + rowid * XSTRIDE + 2 * q) = e;
    }
}

// ---------------- Phase 1: pipelined tf32 mma.sync GEMM ----------------
// block = (i, j-quad); 8 warps; warp w: jj=w>>1, half=w&1 -> 32b x 64o tile.
__global__ __launch_bounds__(256, 2)
void ll_mma_kernel(const float* __restrict__ x,
                   const float* __restrict__ w,
                   const float* __restrict__ bias)
{
    extern __shared__ float smem[];
    uint32_t* smu = (uint32_t*)smem;
    const uint32_t sbase = sptr(smem);

    const int bid  = blockIdx.x;
    const int i    = bid >> 3;
    const int j0   = (bid & 7) << 2;
    const int posb = i * 32 + j0;
    const int t    = threadIdx.x;
    const int lane = t & 31;
    const int warp = t >> 5;
    const int jj   = warp >> 1;
    const int half = warp & 1;
    const int grp  = lane >> 2;
    const int tig  = lane & 3;

    // ---- hoisted per-ks fragment offsets (same per-k formulas, k<36) ----
    int xo1a[5], xo2a[5], wo1a[5], wo2a[5];
#pragma unroll
    for (int ks = 0; ks < 5; ++ks) {
        const int k1 = ks * 8 + tig;           // <= 35: always valid
        {
            const int cl = k1 / 9;
            const int r  = k1 - cl * 9;
            const int u  = r / 3, vv = r - u * 3;
            xo1a[ks] = (cl * 3 + u) * 768 + jj + vv + 1;
            wo1a[ks] = cl * 36 + jj * 9 + r;
        }
        if (ks < 4) {                           // k2 = k1+4 <= 35
            const int k2 = k1 + 4;
            const int cl = k2 / 9;
            const int r  = k2 - cl * 9;
            const int u  = r / 3, vv = r - u * 3;
            xo2a[ks] = (cl * 3 + u) * 768 + jj + vv + 1;
            wo2a[ks] = cl * 36 + jj * 9 + r;
        } else { xo2a[ks] = 0; wo2a[ks] = 0; }
    }

    float acc[2][8][4];
#pragma unroll
    for (int mt = 0; mt < 2; ++mt)
#pragma unroll
        for (int nt = 0; nt < 8; ++nt)
#pragma unroll
            for (int q = 0; q < 4; ++q) acc[mt][nt][q] = 0.f;

    float2 rx[12];

    // ---- prologue: W(0)->buf0 (cp.async), X(0) via regs -> X buffer ----
    stage_w(w, 0, posb, t, sbase);
    load_x(x, 0, i, j0, t, rx);
    CP_WAIT(0);
    store_x(smu + XBASE_F, t, rx);
    __syncthreads();

    for (int ch = 0; ch < NCH; ++ch) {
        const int  buf = ch & 1;
        const bool hn  = (ch + 1 < NCH);

        if (hn) {
            load_x(x, (ch + 1) * CCH, i, j0, t, rx);              // LDG prefetch
            stage_w(w, (ch + 1) * CCH, posb, t,
                    sbase + (uint32_t)((buf ^ 1) * WBUF_F * 4));  // cp.async
        }

        const float*    Wb = smem + buf * WBUF_F;
        const uint32_t* Xb = smu + XBASE_F;

#pragma unroll
        for (int ks = 0; ks < 5; ++ks) {
            const bool v2  = (ks < 4);
            const int  xo1 = xo1a[ks], wo1 = wo1a[ks];
            const int  xo2 = xo2a[ks], wo2 = wo2a[ks];

            uint32_t a[2][4];
#pragma unroll
            for (int mt = 0; mt < 2; ++mt) {
                const int br = half * 32 + mt * 16 + grp;
                a[mt][0] = Xb[xo1 + br * XSTRIDE];
                a[mt][1] = Xb[xo1 + (br + 8) * XSTRIDE];
                a[mt][2] = v2 ? Xb[xo2 + br * XSTRIDE]       : 0u;
                a[mt][3] = v2 ? Xb[xo2 + (br + 8) * XSTRIDE] : 0u;
            }
#pragma unroll
            for (int nt = 0; nt < 8; ++nt) {
                const int o = nt * 8 + grp;
                const float bf0 = Wb[o * WSTRIDE + wo1];
                const float bf1 = v2 ? Wb[o * WSTRIDE + wo2] : 0.f;
                const uint32_t b0 = to_tf32(bf0);
                const uint32_t b1 = to_tf32(bf1);
                mma8(acc[0][nt], a[0], b0, b1);
                mma8(acc[1][nt], a[1], b0, b1);
            }
        }

        __syncthreads();                 // all reads of X(ch) done
        if (hn) store_x(smu + XBASE_F, t, rx);
        CP_WAIT(0);                      // W(ch+1) resident
        __syncthreads();                 // X(ch+1) + W(ch+1) visible
    }

    // ---- epilogue: bias + store yt + fused per-block BN partials ----
    const int pos = posb + jj;
    float* redS = smem;
    float* redQ = smem + 512;

#pragma unroll
    for (int nt = 0; nt < 8; ++nt) {
        const int o0 = nt * 8 + tig * 2;
        const float bs0 = __ldg(bias + o0 * POS + pos);
        const float bs1 = __ldg(bias + (o0 + 1) * POS + pos);
        float y[2][4];
#pragma unroll
        for (int mt = 0; mt < 2; ++mt) {
            y[mt][0] = acc[mt][nt][0] + bs0;
            y[mt][1] = acc[mt][nt][1] + bs1;
            y[mt][2] = acc[mt][nt][2] + bs0;
            y[mt][3] = acc[mt][nt][3] + bs1;
            const int b = half * 32 + mt * 16 + grp;
            g_yt[((size_t)o0 * POS + pos) * B_ + b]           = y[mt][0];
            g_yt[((size_t)(o0 + 1) * POS + pos) * B_ + b]     = y[mt][1];
            g_yt[((size_t)o0 * POS + pos) * B_ + b + 8]       = y[mt][2];
            g_yt[((size_t)(o0 + 1) * POS + pos) * B_ + b + 8] = y[mt][3];
        }
        float se = y[0][0] + y[0][2] + y[1][0] + y[1][2];
        float so = y[0][1] + y[0][3] + y[1][1] + y[1][3];
        float qe = y[0][0]*y[0][0] + y[0][2]*y[0][2] + y[1][0]*y[1][0] + y[1][2]*y[1][2];
        float qo = y[0][1]*y[0][1] + y[0][3]*y[0][3] + y[1][1]*y[1][1] + y[1][3]*y[1][3];
#pragma unroll
        for (int off = 4; off <= 16; off <<= 1) {
            se += __shfl_xor_sync(0xffffffffu, se, off);
            so += __shfl_xor_sync(0xffffffffu, so, off);
            qe += __shfl_xor_sync(0xffffffffu, qe, off);
            qo += __shfl_xor_sync(0xffffffffu, qo, off);
        }
        if (grp == 0) {
            redS[warp * 64 + o0]     = se;
            redS[warp * 64 + o0 + 1] = so;
            redQ[warp * 64 + o0]     = qe;
            redQ[warp * 64 + o0 + 1] = qo;
        }
    }
    __syncthreads();
    if (t < 64) {
        float S = 0.f, Q = 0.f;
#pragma unroll
        for (int ww = 0; ww < 8; ++ww) { S += redS[ww * 64 + t]; Q += redQ[ww * 64 + t]; }
        g_partS[t * 256 + bid] = S;
        g_partQ[t * 256 + bid] = Q;
    }
}

// -------------------- Phase 2: tiny partial reduce --------------------
__global__ __launch_bounds__(256)
void stats2_kernel()
{
    const int o = blockIdx.x;
    const int t = threadIdx.x;
    float s = g_partS[o * 256 + t];
    float q = g_partQ[o * 256 + t];
#pragma unroll
    for (int off = 16; off; off >>= 1) {
        s += __shfl_xor_sync(0xffffffffu, s, off);
        q += __shfl_xor_sync(0xffffffffu, q, off);
    }
    __shared__ float shs[8], shq[8];
    if ((t & 31) == 0) { shs[t >> 5] = s; shq[t >> 5] = q; }
    __syncthreads();
    if (t < 8) {
        s = shs[t]; q = shq[t];
#pragma unroll
        for (int off = 4; off; off >>= 1) {
            s += __shfl_xor_sync(0xffu, s, off);
            q += __shfl_xor_sync(0xffu, q, off);
        }
        if (t == 0) { g_sum[o] = s; g_sumsq[o] = q; }
    }
}

// ------------- Phase 3: BN normalize + ReLU + layout transpose -------------
__global__ __launch_bounds__(256)
void norm_kernel(float* __restrict__ out,
                 const float* __restrict__ gamma,
                 const float* __restrict__ beta)
{
    __shared__ float tile[32][65];
    const int i = blockIdx.x;
    const int o = blockIdx.y;
    const int t = threadIdx.x;

    for (int idx = t; idx < 32 * 64; idx += 256) {
        const int jj = idx >> 6;
        const int bb = idx & 63;
        tile[jj][bb] = g_yt[((size_t)o * POS + i * 32 + jj) * B_ + bb];
    }
    const float invN  = 1.f / (float)(POS * B_);
    const float mean  = g_sum[o] * invN;
    const float var   = g_sumsq[o] * invN - mean * mean;
    const float scale = __ldg(gamma + o) * rsqrtf(var + 1e-5f);
    const float shift = __ldg(beta + o) - mean * scale;
    __syncthreads();

    for (int idx = t; idx < 32 * 64; idx += 256) {
        const int bb = idx >> 5;
        const int jj = idx & 31;
        const float v = tile[jj][bb] * scale + shift;
        out[(((size_t)bb * COUT + o) * IMG + i) * IMG + jj] = fmaxf(v, 0.f);
    }
}

// ---------------------------------------------------------------------------
extern "C" void kernel_launch(void* const* d_in, const int* in_sizes, int n_in,
                              void* d_out, int out_size)
{
    const float* x     = (const float*)d_in[0];
    const float* w     = (const float*)d_in[1];
    const float* bias  = (const float*)d_in[2];
    const float* gamma = (const float*)d_in[3];
    const float* beta  = (const float*)d_in[4];
    float* out = (float*)d_out;

    cudaFuncSetAttribute(ll_mma_kernel,
                         cudaFuncAttributeMaxDynamicSharedMemorySize, SMEM_BYTES);
    ll_mma_kernel<<<256, 256, SMEM_BYTES>>>(x, w, bias);
    stats2_kernel<<<COUT, 256>>>();
    dim3 g3(IMG, COUT);
    norm_kernel<<<g3, 256>>>(out, gamma, beta);
}

// round 14
// speedup vs baseline: 1.2918x; 1.2918x over previous
#include <cuda_runtime.h>
#include <cstdint>

#define B_      64
#define CIN     64
#define COUT    64
#define IMG     32
#define POS     1024
#define CCH     2                 // channels per chunk
#define NCH     32                // 64 / 2
#define WSTRIDE 76                // floats per o-row in W stage (2*36 + 4 pad)
#define WBUF_F  (64 * WSTRIDE)    // 4864 floats per W buffer (x3 ring)
#define XSTRIDE 12                // floats per (g,b) row in X stage (8 used)
#define XBUF_F  (6 * 64 * XSTRIDE) // 4608 floats per X buffer (x2)
#define XBASE_F (3 * WBUF_F)      // 14592
#define SMEM_F  (XBASE_F + 2 * XBUF_F)   // 23808 floats
#define SMEM_BYTES (SMEM_F * 4)          // 95232

__device__ float g_yt[(size_t)COUT * POS * B_];
__device__ float g_partS[COUT * 256];
__device__ float g_partQ[COUT * 256];

__device__ __forceinline__ uint32_t to_tf32(float f) {
    uint32_t r;
    asm("cvt.rna.tf32.f32 %0, %1;" : "=r"(r) : "f"(f));
    return r;
}
__device__ __forceinline__ void mma8(float* c, const uint32_t* a,
                                     uint32_t b0, uint32_t b1) {
    asm volatile(
        "mma.sync.aligned.m16n8k8.row.col.f32.tf32.tf32.f32 "
        "{%0,%1,%2,%3}, {%4,%5,%6,%7}, {%8,%9}, {%0,%1,%2,%3};"
        : "+f"(c[0]), "+f"(c[1]), "+f"(c[2]), "+f"(c[3])
        : "r"(a[0]), "r"(a[1]), "r"(a[2]), "r"(a[3]), "r"(b0), "r"(b1));
}
__device__ __forceinline__ uint32_t sptr(const void* p) {
    uint32_t a;
    asm("{ .reg .u64 t; cvta.to.shared.u64 t, %1; cvt.u32.u64 %0, t; }" : "=r"(a) : "l"(p));
    return a;
}
__device__ __forceinline__ void cp16(uint32_t dst, const void* src) {
    asm volatile("cp.async.cg.shared.global [%0], [%1], 16;"
                 :: "r"(dst), "l"(src) : "memory");
}
#define CP_COMMIT() asm volatile("cp.async.commit_group;" ::: "memory")
#define CP_WAIT(N)  asm volatile("cp.async.wait_group %0;" :: "n"(N) : "memory")

// issue cp.async for one chunk of weights (128 granules x 9 float4) + commit
__device__ __forceinline__ void stage_w(const float* __restrict__ w,
                                        int c0, int posb, int t, uint32_t wdst)
{
    for (int f = t; f < 1152; f += 256) {
        const int go = f / 9;
        const int r  = f - go * 9;
        const int o  = go >> 1, cl = go & 1;
        const float* src = w + ((size_t)(o * CIN + c0 + cl) * POS + posb) * 9 + r * 4;
        cp16(wdst + (uint32_t)((o * WSTRIDE + cl * 36 + r * 4) * 4), src);
    }
    CP_COMMIT();
}

// guarded x loads for one chunk into registers (6 float2 / thread)
__device__ __forceinline__ void load_x(const float* __restrict__ x,
                                       int c0, int i, int j0, int t, float2* rx)
{
#pragma unroll
    for (int l = 0; l < 6; ++l) {
        const int f     = t + l * 256;
        const int q     = f & 3;
        const int rowid = f >> 2;
        const int b     = rowid & 63;
        const int g     = rowid >> 6;      // cl*3+u
        const int cl    = (g >= 3);
        const int u     = g - cl * 3;
        const int row   = i - 1 + u;
        const int col   = j0 - 2 + 2 * q;
        float2 v = make_float2(0.f, 0.f);
        const bool ok = ((unsigned)row < IMG) &&
                        !(q == 0 && j0 == 0) && !(q == 3 && j0 == 28);
        if (ok)
            v = *(const float2*)(x + ((size_t)(b * CIN + c0 + cl) * IMG + row) * IMG + col);
        rx[l] = v;
    }
}

// unconditional STS of prefetched x registers, pre-converted to tf32 bits
__device__ __forceinline__ void store_x(uint32_t* xbuf, int t, const float2* rx)
{
#pragma unroll
    for (int l = 0; l < 6; ++l) {
        const int f     = t + l * 256;
        const int q     = f & 3;
        const int rowid = f >> 2;
        uint2 e;
        e.x = to_tf32(rx[l].x);
        e.y = to_tf32(rx[l].y);
        *(uint2*)(xbuf + rowid * XSTRIDE + 2 * q) = e;
    }
}

// ---------------- Phase 1: pipelined tf32 mma.sync GEMM ----------------
__global__ __launch_bounds__(256, 2)
void ll_mma_kernel(const float* __restrict__ x,
                   const float* __restrict__ w,
                   const float* __restrict__ bias)
{
    extern __shared__ float smem[];
    uint32_t* smu = (uint32_t*)smem;
    const uint32_t sbase = sptr(smem);

    const int bid  = blockIdx.x;
    const int i    = bid >> 3;
    const int j0   = (bid & 7) << 2;
    const int posb = i * 32 + j0;
    const int t    = threadIdx.x;
    const int lane = t & 31;
    const int warp = t >> 5;
    const int jj   = warp >> 1;
    const int half = warp & 1;
    const int grp  = lane >> 2;
    const int tig  = lane & 3;

    // ---- hoisted per-ks fragment offsets (verified round-10 math) ----
    int xo1a[3], xo2a[3], wo1a[3], wo2a[3];
    bool v1a[3];
#pragma unroll
    for (int ks = 0; ks < 3; ++ks) {
        const int k1 = ks * 8 + tig;
        v1a[ks] = (ks < 2) || (tig < 2);
        {
            const int kk = v1a[ks] ? k1 : 0;
            const int cl = (kk >= 9) ? 1 : 0;
            const int r  = kk - cl * 9;
            const int u  = r / 3, vv = r - u * 3;
            xo1a[ks] = (cl * 3 + u) * 768 + jj + vv + 1;
            wo1a[ks] = cl * 36 + jj * 9 + r;
        }
        if (ks < 2) {
            const int k2 = k1 + 4;
            const int cl = (k2 >= 9) ? 1 : 0;
            const int r  = k2 - cl * 9;
            const int u  = r / 3, vv = r - u * 3;
            xo2a[ks] = (cl * 3 + u) * 768 + jj + vv + 1;
            wo2a[ks] = cl * 36 + jj * 9 + r;
        } else { xo2a[ks] = 0; wo2a[ks] = 0; }
    }

    float acc[2][8][4];
#pragma unroll
    for (int mt = 0; mt < 2; ++mt)
#pragma unroll
        for (int nt = 0; nt < 8; ++nt)
#pragma unroll
            for (int q = 0; q < 4; ++q) acc[mt][nt][q] = 0.f;

    float2 rx[6];

    // ---- prologue: W(0)->buf0, W(1)->buf1 (cp.async), X(0)->X0 (regs+STS)
    stage_w(w, 0, posb, t, sbase);
    stage_w(w, CCH, posb, t, sbase + (uint32_t)(WBUF_F * 4));
    load_x(x, 0, i, j0, t, rx);
    store_x(smu + XBASE_F, t, rx);
    CP_WAIT(1);          // W(0) complete
    __syncthreads();

    int wb = 0;          // W ring index of current chunk
#pragma unroll 2
    for (int ch = 0; ch < NCH; ++ch) {
        const int  xb = ch & 1;
        const bool hx = (ch + 1 < NCH);
        const bool hw = (ch + 2 < NCH);

        if (hx) load_x(x, (ch + 1) * CCH, i, j0, t, rx);   // LDG prefetch

        const float*    Wb = smem + wb * WBUF_F;
        const uint32_t* Xb = smu + XBASE_F + xb * XBUF_F;

#pragma unroll
        for (int ks = 0; ks < 3; ++ks) {
            const bool v1  = v1a[ks];
            const int  xo1 = xo1a[ks], wo1 = wo1a[ks];
            const int  xo2 = xo2a[ks], wo2 = wo2a[ks];

            uint32_t a[2][4];
#pragma unroll
            for (int mt = 0; mt < 2; ++mt) {
                const int br = half * 32 + mt * 16 + grp;
                a[mt][0] = v1 ? Xb[xo1 + br * XSTRIDE]       : 0u;
                a[mt][1] = v1 ? Xb[xo1 + (br + 8) * XSTRIDE] : 0u;
                a[mt][2] = (ks < 2) ? Xb[xo2 + br * XSTRIDE]       : 0u;
                a[mt][3] = (ks < 2) ? Xb[xo2 + (br + 8) * XSTRIDE] : 0u;
            }
#pragma unroll
            for (int nt = 0; nt < 8; ++nt) {
                const int o = nt * 8 + grp;
                const float bf0 = v1 ? Wb[o * WSTRIDE + wo1] : 0.f;
                const float bf1 = (ks < 2) ? Wb[o * WSTRIDE + wo2] : 0.f;
                const uint32_t b0 = to_tf32(bf0);
                const uint32_t b1 = to_tf32(bf1);
                mma8(acc[0][nt], a[0], b0, b1);
                mma8(acc[1][nt], a[1], b0, b1);
            }

            if (ks == 0) {   // keep W staging early for overlap
                int wb2 = wb + 2; if (wb2 >= 3) wb2 -= 3;
                if (hw) stage_w(w, (ch + 2) * CCH, posb, t,
                                sbase + (uint32_t)(wb2 * WBUF_F * 4));
                else    CP_COMMIT();          // keep group count uniform
            }
        }

        // X(ch+1) store moved after ks2: LDG gets the full chunk to land
        if (hx) store_x(smu + XBASE_F + (xb ^ 1) * XBUF_F, t, rx);

        CP_WAIT(1);        // W(ch+1) complete (its group committed last iter)
        __syncthreads();   // X(ch+1) STS visible; all reads of old bufs done
        wb = (wb + 1 == 3) ? 0 : wb + 1;
    }
    CP_WAIT(0);

    // ---- epilogue: bias + store yt + fused per-block BN partials ----
    const int pos = posb + jj;
    float* redS = smem;
    float* redQ = smem + 512;

#pragma unroll
    for (int nt = 0; nt < 8; ++nt) {
        const int o0 = nt * 8 + tig * 2;
        const float bs0 = __ldg(bias + o0 * POS + pos);
        const float bs1 = __ldg(bias + (o0 + 1) * POS + pos);
        float y[2][4];
#pragma unroll
        for (int mt = 0; mt < 2; ++mt) {
            y[mt][0] = acc[mt][nt][0] + bs0;
            y[mt][1] = acc[mt][nt][1] + bs1;
            y[mt][2] = acc[mt][nt][2] + bs0;
            y[mt][3] = acc[mt][nt][3] + bs1;
            const int b = half * 32 + mt * 16 + grp;
            g_yt[((size_t)o0 * POS + pos) * B_ + b]           = y[mt][0];
            g_yt[((size_t)(o0 + 1) * POS + pos) * B_ + b]     = y[mt][1];
            g_yt[((size_t)o0 * POS + pos) * B_ + b + 8]       = y[mt][2];
            g_yt[((size_t)(o0 + 1) * POS + pos) * B_ + b + 8] = y[mt][3];
        }
        float se = y[0][0] + y[0][2] + y[1][0] + y[1][2];
        float so = y[0][1] + y[0][3] + y[1][1] + y[1][3];
        float qe = y[0][0]*y[0][0] + y[0][2]*y[0][2] + y[1][0]*y[1][0] + y[1][2]*y[1][2];
        float qo = y[0][1]*y[0][1] + y[0][3]*y[0][3] + y[1][1]*y[1][1] + y[1][3]*y[1][3];
#pragma unroll
        for (int off = 4; off <= 16; off <<= 1) {
            se += __shfl_xor_sync(0xffffffffu, se, off);
            so += __shfl_xor_sync(0xffffffffu, so, off);
            qe += __shfl_xor_sync(0xffffffffu, qe, off);
            qo += __shfl_xor_sync(0xffffffffu, qo, off);
        }
        if (grp == 0) {
            redS[warp * 64 + o0]     = se;
            redS[warp * 64 + o0 + 1] = so;
            redQ[warp * 64 + o0]     = qe;
            redQ[warp * 64 + o0 + 1] = qo;
        }
    }
    __syncthreads();
    if (t < 64) {
        float S = 0.f, Q = 0.f;
#pragma unroll
        for (int ww = 0; ww < 8; ++ww) { S += redS[ww * 64 + t]; Q += redQ[ww * 64 + t]; }
        g_partS[t * 256 + bid] = S;
        g_partQ[t * 256 + bid] = Q;
    }
}

// ---- Phase 2: BN stats (fused reduce) + normalize + ReLU + transpose ----
__global__ __launch_bounds__(256)
void norm_kernel(float* __restrict__ out,
                 const float* __restrict__ gamma,
                 const float* __restrict__ beta)
{
    __shared__ float tile[32][65];
    __shared__ float shs[8], shq[8];
    const int i = blockIdx.x;
    const int o = blockIdx.y;
    const int t = threadIdx.x;

    // per-block redundant reduction of this channel's 256 partials
    float s = g_partS[o * 256 + t];
    float q = g_partQ[o * 256 + t];
#pragma unroll
    for (int off = 16; off; off >>= 1) {
        s += __shfl_xor_sync(0xffffffffu, s, off);
        q += __shfl_xor_sync(0xffffffffu, q, off);
    }
    if ((t & 31) == 0) { shs[t >> 5] = s; shq[t >> 5] = q; }

    for (int idx = t; idx < 32 * 64; idx += 256) {
        const int jj = idx >> 6;
        const int bb = idx & 63;
        tile[jj][bb] = g_yt[((size_t)o * POS + i * 32 + jj) * B_ + bb];
    }
    __syncthreads();

    float S = 0.f, Q = 0.f;
#pragma unroll
    for (int ww = 0; ww < 8; ++ww) { S += shs[ww]; Q += shq[ww]; }

    const float invN  = 1.f / (float)(POS * B_);
    const float mean  = S * invN;
    const float var   = Q * invN - mean * mean;
    const float scale = __ldg(gamma + o) * rsqrtf(var + 1e-5f);
    const float shift = __ldg(beta + o) - mean * scale;

    for (int idx = t; idx < 32 * 64; idx += 256) {
        const int bb = idx >> 5;
        const int jj = idx & 31;
        const float v = tile[jj][bb] * scale + shift;
        out[(((size_t)bb * COUT + o) * IMG + i) * IMG + jj] = fmaxf(v, 0.f);
    }
}

// ---------------------------------------------------------------------------
extern "C" void kernel_launch(void* const* d_in, const int* in_sizes, int n_in,
                              void* d_out, int out_size)
{
    const float* x     = (const float*)d_in[0];
    const float* w     = (const float*)d_in[1];
    const float* bias  = (const float*)d_in[2];
    const float* gamma = (const float*)d_in[3];
    const float* beta  = (const float*)d_in[4];
    float* out = (float*)d_out;

    cudaFuncSetAttribute(ll_mma_kernel,
                         cudaFuncAttributeMaxDynamicSharedMemorySize, SMEM_BYTES);
    ll_mma_kernel<<<256, 256, SMEM_BYTES>>>(x, w, bias);
    dim3 g3(IMG, COUT);
    norm_kernel<<<g3, 256>>>(out, gamma, beta);
}

// round 15
// speedup vs baseline: 1.3343x; 1.0329x over previous
#include <cuda_runtime.h>
#include <cstdint>

#define B_      64
#define CIN     64
#define COUT    64
#define IMG     32
#define POS     1024
#define CCH     2                 // channels per chunk
#define NCH     32                // 64 / 2
#define WSTRIDE 76                // floats per o-row in W stage (2*36 + 4 pad)
#define WBUF_F  (64 * WSTRIDE)    // 4864 floats per W buffer (x3 ring)
#define XSTRIDE 12                // floats per (g,b) row in X stage (8 used)
#define XBUF_F  (6 * 64 * XSTRIDE) // 4608 floats per X buffer (x2)
#define XBASE_F (3 * WBUF_F)      // 14592
#define SMEM_F  (XBASE_F + 2 * XBUF_F)   // 23808 floats
#define SMEM_BYTES (SMEM_F * 4)          // 95232

__device__ float g_yt[(size_t)COUT * POS * B_];
__device__ float g_partS[COUT * 256];
__device__ float g_partQ[COUT * 256];

__device__ __forceinline__ uint32_t to_tf32(float f) {
    uint32_t r;
    asm("cvt.rna.tf32.f32 %0, %1;" : "=r"(r) : "f"(f));
    return r;
}
__device__ __forceinline__ void mma8(float* c, const uint32_t* a,
                                     uint32_t b0, uint32_t b1) {
    asm volatile(
        "mma.sync.aligned.m16n8k8.row.col.f32.tf32.tf32.f32 "
        "{%0,%1,%2,%3}, {%4,%5,%6,%7}, {%8,%9}, {%0,%1,%2,%3};"
        : "+f"(c[0]), "+f"(c[1]), "+f"(c[2]), "+f"(c[3])
        : "r"(a[0]), "r"(a[1]), "r"(a[2]), "r"(a[3]), "r"(b0), "r"(b1));
}
__device__ __forceinline__ uint32_t sptr(const void* p) {
    uint32_t a;
    asm("{ .reg .u64 t; cvta.to.shared.u64 t, %1; cvt.u32.u64 %0, t; }" : "=r"(a) : "l"(p));
    return a;
}
__device__ __forceinline__ void cp16(uint32_t dst, const void* src) {
    asm volatile("cp.async.cg.shared.global [%0], [%1], 16;"
                 :: "r"(dst), "l"(src) : "memory");
}
#define CP_COMMIT() asm volatile("cp.async.commit_group;" ::: "memory")
#define CP_WAIT(N)  asm volatile("cp.async.wait_group %0;" :: "n"(N) : "memory")

// issue cp.async for one chunk of weights (128 granules x 9 float4) + commit
__device__ __forceinline__ void stage_w(const float* __restrict__ w,
                                        int c0, int posb, int t, uint32_t wdst)
{
    for (int f = t; f < 1152; f += 256) {
        const int go = f / 9;
        const int r  = f - go * 9;
        const int o  = go >> 1, cl = go & 1;
        const float* src = w + ((size_t)(o * CIN + c0 + cl) * POS + posb) * 9 + r * 4;
        cp16(wdst + (uint32_t)((o * WSTRIDE + cl * 36 + r * 4) * 4), src);
    }
    CP_COMMIT();
}

// guarded x loads for one chunk into registers (6 float2 / thread)
__device__ __forceinline__ void load_x(const float* __restrict__ x,
                                       int c0, int i, int j0, int t, float2* rx)
{
#pragma unroll
    for (int l = 0; l < 6; ++l) {
        const int f     = t + l * 256;
        const int q     = f & 3;
        const int rowid = f >> 2;
        const int b     = rowid & 63;
        const int g     = rowid >> 6;      // cl*3+u
        const int cl    = (g >= 3);
        const int u     = g - cl * 3;
        const int row   = i - 1 + u;
        const int col   = j0 - 2 + 2 * q;
        float2 v = make_float2(0.f, 0.f);
        const bool ok = ((unsigned)row < IMG) &&
                        !(q == 0 && j0 == 0) && !(q == 3 && j0 == 28);
        if (ok)
            v = *(const float2*)(x + ((size_t)(b * CIN + c0 + cl) * IMG + row) * IMG + col);
        rx[l] = v;
    }
}

// unconditional STS of prefetched x registers, pre-converted to tf32 bits
__device__ __forceinline__ void store_x(uint32_t* xbuf, int t, const float2* rx)
{
#pragma unroll
    for (int l = 0; l < 6; ++l) {
        const int f     = t + l * 256;
        const int q     = f & 3;
        const int rowid = f >> 2;
        uint2 e;
        e.x = to_tf32(rx[l].x);
        e.y = to_tf32(rx[l].y);
        *(uint2*)(xbuf + rowid * XSTRIDE + 2 * q) = e;
    }
}

// ---------------- Phase 1: pipelined tf32 mma.sync GEMM ----------------
__global__ __launch_bounds__(256, 2)
void ll_mma_kernel(const float* __restrict__ x,
                   const float* __restrict__ w,
                   const float* __restrict__ bias)
{
    extern __shared__ float smem[];
    uint32_t* smu = (uint32_t*)smem;
    const uint32_t sbase = sptr(smem);

    const int bid  = blockIdx.x;
    const int i    = bid >> 3;
    const int j0   = (bid & 7) << 2;
    const int posb = i * 32 + j0;
    const int t    = threadIdx.x;
    const int lane = t & 31;
    const int warp = t >> 5;
    const int jj   = warp >> 1;
    const int half = warp & 1;
    const int grp  = lane >> 2;
    const int tig  = lane & 3;

    // ---- hoisted per-ks fragment offsets (verified round-10 math) ----
    int xo1a[3], xo2a[3], wo1a[3], wo2a[3];
    bool v1a[3];
#pragma unroll
    for (int ks = 0; ks < 3; ++ks) {
        const int k1 = ks * 8 + tig;
        v1a[ks] = (ks < 2) || (tig < 2);
        {
            const int kk = v1a[ks] ? k1 : 0;
            const int cl = (kk >= 9) ? 1 : 0;
            const int r  = kk - cl * 9;
            const int u  = r / 3, vv = r - u * 3;
            xo1a[ks] = (cl * 3 + u) * 768 + jj + vv + 1;
            wo1a[ks] = cl * 36 + jj * 9 + r;
        }
        if (ks < 2) {
            const int k2 = k1 + 4;
            const int cl = (k2 >= 9) ? 1 : 0;
            const int r  = k2 - cl * 9;
            const int u  = r / 3, vv = r - u * 3;
            xo2a[ks] = (cl * 3 + u) * 768 + jj + vv + 1;
            wo2a[ks] = cl * 36 + jj * 9 + r;
        } else { xo2a[ks] = 0; wo2a[ks] = 0; }
    }

    float acc[2][8][4];
#pragma unroll
    for (int mt = 0; mt < 2; ++mt)
#pragma unroll
        for (int nt = 0; nt < 8; ++nt)
#pragma unroll
            for (int q = 0; q < 4; ++q) acc[mt][nt][q] = 0.f;

    float2 rx[6];

    // ---- prologue: W(0)->buf0, W(1)->buf1 (cp.async), X(0)->X0 (regs+STS)
    stage_w(w, 0, posb, t, sbase);
    stage_w(w, CCH, posb, t, sbase + (uint32_t)(WBUF_F * 4));
    load_x(x, 0, i, j0, t, rx);
    store_x(smu + XBASE_F, t, rx);
    CP_WAIT(1);          // W(0) complete
    __syncthreads();

    int wb = 0;          // W ring index of current chunk
#pragma unroll 2
    for (int ch = 0; ch < NCH; ++ch) {
        const int  xb = ch & 1;
        const bool hx = (ch + 1 < NCH);
        const bool hw = (ch + 2 < NCH);

        if (hx) load_x(x, (ch + 1) * CCH, i, j0, t, rx);   // LDG prefetch

        const float*    Wb = smem + wb * WBUF_F;
        const uint32_t* Xb = smu + XBASE_F + xb * XBUF_F;

#pragma unroll
        for (int ks = 0; ks < 3; ++ks) {
            const bool v1  = v1a[ks];
            const int  xo1 = xo1a[ks], wo1 = wo1a[ks];
            const int  xo2 = xo2a[ks], wo2 = wo2a[ks];

            uint32_t a[2][4];
#pragma unroll
            for (int mt = 0; mt < 2; ++mt) {
                const int br = half * 32 + mt * 16 + grp;
                a[mt][0] = v1 ? Xb[xo1 + br * XSTRIDE]       : 0u;
                a[mt][1] = v1 ? Xb[xo1 + (br + 8) * XSTRIDE] : 0u;
                a[mt][2] = (ks < 2) ? Xb[xo2 + br * XSTRIDE]       : 0u;
                a[mt][3] = (ks < 2) ? Xb[xo2 + (br + 8) * XSTRIDE] : 0u;
            }
#pragma unroll
            for (int nt = 0; nt < 8; ++nt) {
                const int o = nt * 8 + grp;
                const float bf0 = v1 ? Wb[o * WSTRIDE + wo1] : 0.f;
                const float bf1 = (ks < 2) ? Wb[o * WSTRIDE + wo2] : 0.f;
                const uint32_t b0 = to_tf32(bf0);
                const uint32_t b1 = to_tf32(bf1);
                mma8(acc[0][nt], a[0], b0, b1);
                mma8(acc[1][nt], a[1], b0, b1);
            }

            if (ks == 0) {   // keep W staging early for overlap
                int wb2 = wb + 2; if (wb2 >= 3) wb2 -= 3;
                if (hw) stage_w(w, (ch + 2) * CCH, posb, t,
                                sbase + (uint32_t)(wb2 * WBUF_F * 4));
                else    CP_COMMIT();          // keep group count uniform
            }
        }

        // X(ch+1) store after ks2: LDG gets the full chunk to land
        if (hx) store_x(smu + XBASE_F + (xb ^ 1) * XBUF_F, t, rx);

        CP_WAIT(1);        // W(ch+1) complete (its group committed last iter)
        __syncthreads();   // X(ch+1) STS visible; all reads of old bufs done
        wb = (wb + 1 == 3) ? 0 : wb + 1;
    }
    CP_WAIT(0);

    // ---- epilogue: bias + store yt + fused per-block BN partials ----
    const int pos = posb + jj;
    float* redS = smem;
    float* redQ = smem + 512;

#pragma unroll
    for (int nt = 0; nt < 8; ++nt) {
        const int o0 = nt * 8 + tig * 2;
        const float bs0 = __ldg(bias + o0 * POS + pos);
        const float bs1 = __ldg(bias + (o0 + 1) * POS + pos);
        float y[2][4];
#pragma unroll
        for (int mt = 0; mt < 2; ++mt) {
            y[mt][0] = acc[mt][nt][0] + bs0;
            y[mt][1] = acc[mt][nt][1] + bs1;
            y[mt][2] = acc[mt][nt][2] + bs0;
            y[mt][3] = acc[mt][nt][3] + bs1;
            const int b = half * 32 + mt * 16 + grp;
            g_yt[((size_t)o0 * POS + pos) * B_ + b]           = y[mt][0];
            g_yt[((size_t)(o0 + 1) * POS + pos) * B_ + b]     = y[mt][1];
            g_yt[((size_t)o0 * POS + pos) * B_ + b + 8]       = y[mt][2];
            g_yt[((size_t)(o0 + 1) * POS + pos) * B_ + b + 8] = y[mt][3];
        }
        float se = y[0][0] + y[0][2] + y[1][0] + y[1][2];
        float so = y[0][1] + y[0][3] + y[1][1] + y[1][3];
        float qe = y[0][0]*y[0][0] + y[0][2]*y[0][2] + y[1][0]*y[1][0] + y[1][2]*y[1][2];
        float qo = y[0][1]*y[0][1] + y[0][3]*y[0][3] + y[1][1]*y[1][1] + y[1][3]*y[1][3];
#pragma unroll
        for (int off = 4; off <= 16; off <<= 1) {
            se += __shfl_xor_sync(0xffffffffu, se, off);
            so += __shfl_xor_sync(0xffffffffu, so, off);
            qe += __shfl_xor_sync(0xffffffffu, qe, off);
            qo += __shfl_xor_sync(0xffffffffu, qo, off);
        }
        if (grp == 0) {
            redS[warp * 64 + o0]     = se;
            redS[warp * 64 + o0 + 1] = so;
            redQ[warp * 64 + o0]     = qe;
            redQ[warp * 64 + o0 + 1] = qo;
        }
    }
    __syncthreads();
    if (t < 64) {
        float S = 0.f, Q = 0.f;
#pragma unroll
        for (int ww = 0; ww < 8; ++ww) { S += redS[ww * 64 + t]; Q += redQ[ww * 64 + t]; }
        g_partS[t * 256 + bid] = S;
        g_partQ[t * 256 + bid] = Q;
    }
}

// ---- Phase 2: BN stats (fused reduce) + normalize + ReLU + transpose ----
// Vectorized: LDG.128 from yt, smem transpose (stride 65), STG.128 to out.
__global__ __launch_bounds__(256)
void norm_kernel(float* __restrict__ out,
                 const float* __restrict__ gamma,
                 const float* __restrict__ beta)
{
    __shared__ float tile[32 * 65];
    __shared__ float shs[8], shq[8];
    const int i = blockIdx.x;
    const int o = blockIdx.y;
    const int t = threadIdx.x;

    // per-block redundant reduction of this channel's 256 partials
    float s = g_partS[o * 256 + t];
    float q = g_partQ[o * 256 + t];
#pragma unroll
    for (int off = 16; off; off >>= 1) {
        s += __shfl_xor_sync(0xffffffffu, s, off);
        q += __shfl_xor_sync(0xffffffffu, q, off);
    }
    if ((t & 31) == 0) { shs[t >> 5] = s; shq[t >> 5] = q; }

    // load: 2 x LDG.128 per thread, scatter to tile[jj][bb] (stride 65)
#pragma unroll
    for (int k = 0; k < 2; ++k) {
        const int idx4 = t + k * 256;       // 0..511
        const int jj   = idx4 >> 4;         // 0..31
        const int bb4  = idx4 & 15;         // 0..15
        const float4 v = *(const float4*)(
            g_yt + ((size_t)o * POS + i * 32 + jj) * B_ + bb4 * 4);
        float* dst = tile + jj * 65 + bb4 * 4;
        dst[0] = v.x; dst[1] = v.y; dst[2] = v.z; dst[3] = v.w;
    }
    __syncthreads();

    float S = 0.f, Q = 0.f;
#pragma unroll
    for (int ww = 0; ww < 8; ++ww) { S += shs[ww]; Q += shq[ww]; }

    const float invN  = 1.f / (float)(POS * B_);
    const float mean  = S * invN;
    const float var   = Q * invN - mean * mean;
    const float scale = __ldg(gamma + o) * rsqrtf(var + 1e-5f);
    const float shift = __ldg(beta + o) - mean * scale;

    // store: gather j-quad column (4 LDS, conflict-free), STG.128 to out
#pragma unroll
    for (int k = 0; k < 2; ++k) {
        const int idx4 = t + k * 256;       // 0..511
        const int bb   = idx4 >> 3;         // 0..63
        const int jq   = idx4 & 7;          // 0..7
        float4 v;
        v.x = tile[(jq * 4 + 0) * 65 + bb];
        v.y = tile[(jq * 4 + 1) * 65 + bb];
        v.z = tile[(jq * 4 + 2) * 65 + bb];
        v.w = tile[(jq * 4 + 3) * 65 + bb];
        v.x = fmaxf(v.x * scale + shift, 0.f);
        v.y = fmaxf(v.y * scale + shift, 0.f);
        v.z = fmaxf(v.z * scale + shift, 0.f);
        v.w = fmaxf(v.w * scale + shift, 0.f);
        *(float4*)(out + (((size_t)bb * COUT + o) * IMG + i) * IMG + jq * 4) = v;
    }
}

// ---------------------------------------------------------------------------
extern "C" void kernel_launch(void* const* d_in, const int* in_sizes, int n_in,
                              void* d_out, int out_size)
{
    const float* x     = (const float*)d_in[0];
    const float* w     = (const float*)d_in[1];
    const float* bias  = (const float*)d_in[2];
    const float* gamma = (const float*)d_in[3];
    const float* beta  = (const float*)d_in[4];
    float* out = (float*)d_out;

    cudaFuncSetAttribute(ll_mma_kernel,
                         cudaFuncAttributeMaxDynamicSharedMemorySize, SMEM_BYTES);
    ll_mma_kernel<<<256, 256, SMEM_BYTES>>>(x, w, bias);
    dim3 g3(IMG, COUT);
    norm_kernel<<<g3, 256>>>(out, gamma, beta);
}

// round 16
// speedup vs baseline: 1.3358x; 1.0011x over previous
#include <cuda_runtime.h>
#include <cuda_fp16.h>
#include <cstdint>

#define B_      64
#define CIN     64
#define COUT    64
#define IMG     32
#define POS     1024
#define CCH     2                 // channels per chunk
#define NCH     32                // 64 / 2
#define WSTRIDE 76                // floats per o-row in W stage (2*36 + 4 pad)
#define WBUF_F  (64 * WSTRIDE)    // 4864 floats per W buffer (x3 ring)
#define XSTRIDE 12                // floats per (g,b) row in X stage (8 used)
#define XBUF_F  (6 * 64 * XSTRIDE) // 4608 floats per X buffer (x2)
#define XBASE_F (3 * WBUF_F)      // 14592
#define SMEM_F  (XBASE_F + 2 * XBUF_F)   // 23808 floats
#define SMEM_BYTES (SMEM_F * 4)          // 95232

__device__ __half g_yt[(size_t)COUT * POS * B_];   // fp16 intermediate
__device__ float  g_partS[COUT * 256];
__device__ float  g_partQ[COUT * 256];

__device__ __forceinline__ uint32_t to_tf32(float f) {
    uint32_t r;
    asm("cvt.rna.tf32.f32 %0, %1;" : "=r"(r) : "f"(f));
    return r;
}
__device__ __forceinline__ void mma8(float* c, const uint32_t* a,
                                     uint32_t b0, uint32_t b1) {
    asm volatile(
        "mma.sync.aligned.m16n8k8.row.col.f32.tf32.tf32.f32 "
        "{%0,%1,%2,%3}, {%4,%5,%6,%7}, {%8,%9}, {%0,%1,%2,%3};"
        : "+f"(c[0]), "+f"(c[1]), "+f"(c[2]), "+f"(c[3])
        : "r"(a[0]), "r"(a[1]), "r"(a[2]), "r"(a[3]), "r"(b0), "r"(b1));
}
__device__ __forceinline__ uint32_t sptr(const void* p) {
    uint32_t a;
    asm("{ .reg .u64 t; cvta.to.shared.u64 t, %1; cvt.u32.u64 %0, t; }" : "=r"(a) : "l"(p));
    return a;
}
__device__ __forceinline__ void cp16(uint32_t dst, const void* src) {
    asm volatile("cp.async.cg.shared.global [%0], [%1], 16;"
                 :: "r"(dst), "l"(src) : "memory");
}
#define CP_COMMIT() asm volatile("cp.async.commit_group;" ::: "memory")
#define CP_WAIT(N)  asm volatile("cp.async.wait_group %0;" :: "n"(N) : "memory")

// issue cp.async for one chunk of weights (128 granules x 9 float4) + commit
__device__ __forceinline__ void stage_w(const float* __restrict__ w,
                                        int c0, int posb, int t, uint32_t wdst)
{
    for (int f = t; f < 1152; f += 256) {
        const int go = f / 9;
        const int r  = f - go * 9;
        const int o  = go >> 1, cl = go & 1;
        const float* src = w + ((size_t)(o * CIN + c0 + cl) * POS + posb) * 9 + r * 4;
        cp16(wdst + (uint32_t)((o * WSTRIDE + cl * 36 + r * 4) * 4), src);
    }
    CP_COMMIT();
}

// guarded x loads for one chunk into registers (6 float2 / thread)
__device__ __forceinline__ void load_x(const float* __restrict__ x,
                                       int c0, int i, int j0, int t, float2* rx)
{
#pragma unroll
    for (int l = 0; l < 6; ++l) {
        const int f     = t + l * 256;
        const int q     = f & 3;
        const int rowid = f >> 2;
        const int b     = rowid & 63;
        const int g     = rowid >> 6;      // cl*3+u
        const int cl    = (g >= 3);
        const int u     = g - cl * 3;
        const int row   = i - 1 + u;
        const int col   = j0 - 2 + 2 * q;
        float2 v = make_float2(0.f, 0.f);
        const bool ok = ((unsigned)row < IMG) &&
                        !(q == 0 && j0 == 0) && !(q == 3 && j0 == 28);
        if (ok)
            v = *(const float2*)(x + ((size_t)(b * CIN + c0 + cl) * IMG + row) * IMG + col);
        rx[l] = v;
    }
}

// unconditional STS of prefetched x registers, pre-converted to tf32 bits
__device__ __forceinline__ void store_x(uint32_t* xbuf, int t, const float2* rx)
{
#pragma unroll
    for (int l = 0; l < 6; ++l) {
        const int f     = t + l * 256;
        const int q     = f & 3;
        const int rowid = f >> 2;
        uint2 e;
        e.x = to_tf32(rx[l].x);
        e.y = to_tf32(rx[l].y);
        *(uint2*)(xbuf + rowid * XSTRIDE + 2 * q) = e;
    }
}

// ---------------- Phase 1: pipelined tf32 mma.sync GEMM ----------------
__global__ __launch_bounds__(256, 2)
void ll_mma_kernel(const float* __restrict__ x,
                   const float* __restrict__ w,
                   const float* __restrict__ bias)
{
    extern __shared__ float smem[];
    uint32_t* smu = (uint32_t*)smem;
    const uint32_t sbase = sptr(smem);

    const int bid  = blockIdx.x;
    const int i    = bid >> 3;
    const int j0   = (bid & 7) << 2;
    const int posb = i * 32 + j0;
    const int t    = threadIdx.x;
    const int lane = t & 31;
    const int warp = t >> 5;
    const int jj   = warp >> 1;
    const int half = warp & 1;
    const int grp  = lane >> 2;
    const int tig  = lane & 3;

    // ---- hoisted per-ks fragment offsets (verified round-10 math) ----
    int xo1a[3], xo2a[3], wo1a[3], wo2a[3];
    bool v1a[3];
#pragma unroll
    for (int ks = 0; ks < 3; ++ks) {
        const int k1 = ks * 8 + tig;
        v1a[ks] = (ks < 2) || (tig < 2);
        {
            const int kk = v1a[ks] ? k1 : 0;
            const int cl = (kk >= 9) ? 1 : 0;
            const int r  = kk - cl * 9;
            const int u  = r / 3, vv = r - u * 3;
            xo1a[ks] = (cl * 3 + u) * 768 + jj + vv + 1;
            wo1a[ks] = cl * 36 + jj * 9 + r;
        }
        if (ks < 2) {
            const int k2 = k1 + 4;
            const int cl = (k2 >= 9) ? 1 : 0;
            const int r  = k2 - cl * 9;
            const int u  = r / 3, vv = r - u * 3;
            xo2a[ks] = (cl * 3 + u) * 768 + jj + vv + 1;
            wo2a[ks] = cl * 36 + jj * 9 + r;
        } else { xo2a[ks] = 0; wo2a[ks] = 0; }
    }

    float acc[2][8][4];
#pragma unroll
    for (int mt = 0; mt < 2; ++mt)
#pragma unroll
        for (int nt = 0; nt < 8; ++nt)
#pragma unroll
            for (int q = 0; q < 4; ++q) acc[mt][nt][q] = 0.f;

    float2 rx[6];

    // ---- prologue: W(0)->buf0, W(1)->buf1 (cp.async), X(0)->X0 (regs+STS)
    stage_w(w, 0, posb, t, sbase);
    stage_w(w, CCH, posb, t, sbase + (uint32_t)(WBUF_F * 4));
    load_x(x, 0, i, j0, t, rx);
    store_x(smu + XBASE_F, t, rx);
    CP_WAIT(1);          // W(0) complete
    __syncthreads();

    int wb = 0;          // W ring index of current chunk
#pragma unroll 2
    for (int ch = 0; ch < NCH; ++ch) {
        const int  xb = ch & 1;
        const bool hx = (ch + 1 < NCH);
        const bool hw = (ch + 2 < NCH);

        if (hx) load_x(x, (ch + 1) * CCH, i, j0, t, rx);   // LDG prefetch

        const float*    Wb = smem + wb * WBUF_F;
        const uint32_t* Xb = smu + XBASE_F + xb * XBUF_F;

#pragma unroll
        for (int ks = 0; ks < 3; ++ks) {
            const bool v1  = v1a[ks];
            const int  xo1 = xo1a[ks], wo1 = wo1a[ks];
            const int  xo2 = xo2a[ks], wo2 = wo2a[ks];

            uint32_t a[2][4];
#pragma unroll
            for (int mt = 0; mt < 2; ++mt) {
                const int br = half * 32 + mt * 16 + grp;
                a[mt][0] = v1 ? Xb[xo1 + br * XSTRIDE]       : 0u;
                a[mt][1] = v1 ? Xb[xo1 + (br + 8) * XSTRIDE] : 0u;
                a[mt][2] = (ks < 2) ? Xb[xo2 + br * XSTRIDE]       : 0u;
                a[mt][3] = (ks < 2) ? Xb[xo2 + (br + 8) * XSTRIDE] : 0u;
            }
#pragma unroll
            for (int nt = 0; nt < 8; ++nt) {
                const int o = nt * 8 + grp;
                const float bf0 = v1 ? Wb[o * WSTRIDE + wo1] : 0.f;
                const float bf1 = (ks < 2) ? Wb[o * WSTRIDE + wo2] : 0.f;
                const uint32_t b0 = to_tf32(bf0);
                const uint32_t b1 = to_tf32(bf1);
                mma8(acc[0][nt], a[0], b0, b1);
                mma8(acc[1][nt], a[1], b0, b1);
            }

            if (ks == 0) {   // keep W staging early for overlap
                int wb2 = wb + 2; if (wb2 >= 3) wb2 -= 3;
                if (hw) stage_w(w, (ch + 2) * CCH, posb, t,
                                sbase + (uint32_t)(wb2 * WBUF_F * 4));
                else    CP_COMMIT();          // keep group count uniform
            }
        }

        // X(ch+1) store after ks2: LDG gets the full chunk to land
        if (hx) store_x(smu + XBASE_F + (xb ^ 1) * XBUF_F, t, rx);

        CP_WAIT(1);        // W(ch+1) complete (its group committed last iter)
        __syncthreads();   // X(ch+1) STS visible; all reads of old bufs done
        wb = (wb + 1 == 3) ? 0 : wb + 1;
    }
    CP_WAIT(0);

    // ---- epilogue: bias + fp16 store yt + fused per-block BN partials ----
    const int pos = posb + jj;
    float* redS = smem;
    float* redQ = smem + 512;

#pragma unroll
    for (int nt = 0; nt < 8; ++nt) {
        const int o0 = nt * 8 + tig * 2;
        const float bs0 = __ldg(bias + o0 * POS + pos);
        const float bs1 = __ldg(bias + (o0 + 1) * POS + pos);
        float y[2][4];
#pragma unroll
        for (int mt = 0; mt < 2; ++mt) {
            y[mt][0] = acc[mt][nt][0] + bs0;
            y[mt][1] = acc[mt][nt][1] + bs1;
            y[mt][2] = acc[mt][nt][2] + bs0;
            y[mt][3] = acc[mt][nt][3] + bs1;
            const int b = half * 32 + mt * 16 + grp;
            g_yt[((size_t)o0 * POS + pos) * B_ + b]           = __float2half_rn(y[mt][0]);
            g_yt[((size_t)(o0 + 1) * POS + pos) * B_ + b]     = __float2half_rn(y[mt][1]);
            g_yt[((size_t)o0 * POS + pos) * B_ + b + 8]       = __float2half_rn(y[mt][2]);
            g_yt[((size_t)(o0 + 1) * POS + pos) * B_ + b + 8] = __float2half_rn(y[mt][3]);
        }
        float se = y[0][0] + y[0][2] + y[1][0] + y[1][2];
        float so = y[0][1] + y[0][3] + y[1][1] + y[1][3];
        float qe = y[0][0]*y[0][0] + y[0][2]*y[0][2] + y[1][0]*y[1][0] + y[1][2]*y[1][2];
        float qo = y[0][1]*y[0][1] + y[0][3]*y[0][3] + y[1][1]*y[1][1] + y[1][3]*y[1][3];
#pragma unroll
        for (int off = 4; off <= 16; off <<= 1) {
            se += __shfl_xor_sync(0xffffffffu, se, off);
            so += __shfl_xor_sync(0xffffffffu, so, off);
            qe += __shfl_xor_sync(0xffffffffu, qe, off);
            qo += __shfl_xor_sync(0xffffffffu, qo, off);
        }
        if (grp == 0) {
            redS[warp * 64 + o0]     = se;
            redS[warp * 64 + o0 + 1] = so;
            redQ[warp * 64 + o0]     = qe;
            redQ[warp * 64 + o0 + 1] = qo;
        }
    }
    __syncthreads();
    if (t < 64) {
        float S = 0.f, Q = 0.f;
#pragma unroll
        for (int ww = 0; ww < 8; ++ww) { S += redS[ww * 64 + t]; Q += redQ[ww * 64 + t]; }
        g_partS[t * 256 + bid] = S;
        g_partQ[t * 256 + bid] = Q;
    }
}

// ---- Phase 2: BN stats (fused reduce) + normalize + ReLU + transpose ----
// fp16 yt: one LDG.128 loads 8 values; fp32 out via STG.128.
__global__ __launch_bounds__(256)
void norm_kernel(float* __restrict__ out,
                 const float* __restrict__ gamma,
                 const float* __restrict__ beta)
{
    __shared__ float tile[32 * 65];
    __shared__ float shs[8], shq[8];
    const int i = blockIdx.x;
    const int o = blockIdx.y;
    const int t = threadIdx.x;

    // per-block redundant reduction of this channel's 256 partials
    float s = g_partS[o * 256 + t];
    float q = g_partQ[o * 256 + t];
#pragma unroll
    for (int off = 16; off; off >>= 1) {
        s += __shfl_xor_sync(0xffffffffu, s, off);
        q += __shfl_xor_sync(0xffffffffu, q, off);
    }
    if ((t & 31) == 0) { shs[t >> 5] = s; shq[t >> 5] = q; }

    // load: 1 x LDG.128 per thread = 8 halfs, scatter to tile (stride 65)
    {
        const int jj = t >> 3;          // 0..31
        const int b8 = (t & 7) * 8;     // 0..56
        const uint4 raw = *(const uint4*)(
            g_yt + ((size_t)o * POS + i * 32 + jj) * B_ + b8);
        const __half2* h2 = (const __half2*)&raw;
        float* dst = tile + jj * 65 + b8;
#pragma unroll
        for (int m = 0; m < 4; ++m) {
            const float2 f = __half22float2(h2[m]);
            dst[2 * m]     = f.x;
            dst[2 * m + 1] = f.y;
        }
    }
    __syncthreads();

    float S = 0.f, Q = 0.f;
#pragma unroll
    for (int ww = 0; ww < 8; ++ww) { S += shs[ww]; Q += shq[ww]; }

    const float invN  = 1.f / (float)(POS * B_);
    const float mean  = S * invN;
    const float var   = Q * invN - mean * mean;
    const float scale = __ldg(gamma + o) * rsqrtf(var + 1e-5f);
    const float shift = __ldg(beta + o) - mean * scale;

    // store: gather j-quad column (4 LDS, conflict-free), STG.128 to out
#pragma unroll
    for (int k = 0; k < 2; ++k) {
        const int idx4 = t + k * 256;       // 0..511
        const int bb   = idx4 >> 3;         // 0..63
        const int jq   = idx4 & 7;          // 0..7
        float4 v;
        v.x = tile[(jq * 4 + 0) * 65 + bb];
        v.y = tile[(jq * 4 + 1) * 65 + bb];
        v.z = tile[(jq * 4 + 2) * 65 + bb];
        v.w = tile[(jq * 4 + 3) * 65 + bb];
        v.x = fmaxf(v.x * scale + shift, 0.f);
        v.y = fmaxf(v.y * scale + shift, 0.f);
        v.z = fmaxf(v.z * scale + shift, 0.f);
        v.w = fmaxf(v.w * scale + shift, 0.f);
        *(float4*)(out + (((size_t)bb * COUT + o) * IMG + i) * IMG + jq * 4) = v;
    }
}

// ---------------------------------------------------------------------------
extern "C" void kernel_launch(void* const* d_in, const int* in_sizes, int n_in,
                              void* d_out, int out_size)
{
    const float* x     = (const float*)d_in[0];
    const float* w     = (const float*)d_in[1];
    const float* bias  = (const float*)d_in[2];
    const float* gamma = (const float*)d_in[3];
    const float* beta  = (const float*)d_in[4];
    float* out = (float*)d_out;

    cudaFuncSetAttribute(ll_mma_kernel,
                         cudaFuncAttributeMaxDynamicSharedMemorySize, SMEM_BYTES);
    ll_mma_kernel<<<256, 256, SMEM_BYTES>>>(x, w, bias);
    dim3 g3(IMG, COUT);
    norm_kernel<<<g3, 256>>>(out, gamma, beta);
}